// round 17
// baseline (speedup 1.0000x reference)
#include <cuda_runtime.h>
#include <math.h>

#define BB   8
#define NN   4096
#define TPB  256
#define QPT  4                     // queries per thread
#define QPB  (TPB * QPT)           // 1024 queries per item
#define NQCH (NN / QPB)            // 4 query chunks
#define NTCH 16                    // target chunks
#define TGT  (NN / NTCH)           // 256 targets per item
#define TILE_P (TGT / 2)           // 128 packed target-pairs (4 KB smem)
#define NITEMS (2 * BB * NQCH * NTCH)   // 1024 work items
#define NBLK_CH 444                // persistent chamfer blocks (3 per SM)
#define NRED_BLK 64
#define QTOT (2 * BB * NN)         // 65536 query slots

typedef unsigned long long ull;
typedef unsigned int uint;

// Scratch (__device__ globals; allocation forbidden).
// g_menc: ~enc_f(min + h_q), combined via atomicMax (exact, order-independent
// -> deterministic). Identity is 0: zero-init valid on call 1; k_reduce resets
// slots to 0 after reading -> self-initializing every replay. Keys are > 0.
__device__ uint  g_menc[QTOT];            // 256 KB
__device__ float g_partials[NRED_BLK];
__device__ uint  g_work = 0;
__device__ uint  g_done = 0;

// ---- packed f32x2 helpers (sm_103a) --------------------------------------
__device__ __forceinline__ ull fma2(ull a, ull b, ull c) {
    ull d;
    asm("fma.rn.f32x2 %0, %1, %2, %3;" : "=l"(d) : "l"(a), "l"(b), "l"(c));
    return d;
}
__device__ __forceinline__ ull pack2(float lo, float hi) {
    ull r;
    asm("mov.b64 %0, {%1, %2};" : "=l"(r) : "f"(lo), "f"(hi));
    return r;
}
__device__ __forceinline__ void unpack2(ull v, float& lo, float& hi) {
    asm("mov.b64 {%0, %1}, %2;" : "=f"(lo), "=f"(hi) : "l"(v));
}
// order-preserving float<->uint encode (no NaNs in this workload)
__device__ __forceinline__ uint enc_f(float f) {
    uint u = __float_as_uint(f);
    return ((int)u >= 0) ? (u ^ 0x80000000u) : ~u;
}
__device__ __forceinline__ float dec_f(uint k) {
    return (k & 0x80000000u) ? __uint_as_float(k ^ 0x80000000u)
                             : __uint_as_float(~k);
}
// 16B global->shared async copy (Ampere+ LDGSTS path)
__device__ __forceinline__ void cp_async16(uint smem_dst, const void* gsrc) {
    asm volatile("cp.async.cg.shared.global [%0], [%1], 16;\n"
                 :: "r"(smem_dst), "l"(gsrc) : "memory");
}
__device__ __forceinline__ void cp_async_commit() {
    asm volatile("cp.async.commit_group;" ::: "memory");
}
__device__ __forceinline__ void cp_async_wait0() {
    asm volatile("cp.async.wait_group 0;" ::: "memory");
}

// Compute both relative transforms for batch b into sR/sT (called by 16 thr)
__device__ __forceinline__ void rel_transform_16(
    int tid,
    const float* __restrict__ pred_rot,   const float* __restrict__ pred_trans,
    const float* __restrict__ ctx_hyp_rot,const float* __restrict__ ctx_hyp_trans,
    const float* __restrict__ gt_rot,     const float* __restrict__ gt_trans,
    const float* __restrict__ ctx_gt_rot, const float* __restrict__ ctx_gt_trans,
    float sR[2][BB][9], float sT[2][BB][3])
{
    const int w = tid / BB, b = tid % BB;
    const float* Ra = (w == 0 ? pred_rot      : gt_rot)       + b * 9;
    const float* ta = (w == 0 ? pred_trans    : gt_trans)     + b * 3;
    const float* Rb = (w == 0 ? ctx_hyp_rot   : ctx_gt_rot)   + b * 9;
    const float* tb = (w == 0 ? ctx_hyp_trans : ctx_gt_trans) + b * 3;
    #pragma unroll
    for (int i = 0; i < 3; i++)
        #pragma unroll
        for (int k = 0; k < 3; k++) {
            float s = 0.f;
            #pragma unroll
            for (int j = 0; j < 3; j++) s += Ra[i*3+j] * Rb[k*3+j];
            sR[w][b][i*3+k] = s;
        }
    #pragma unroll
    for (int i = 0; i < 3; i++) {
        float s = ta[i];
        #pragma unroll
        for (int j = 0; j < 3; j++) s -= sR[w][b][i*3+j] * tb[j];
        sT[w][b][i] = s;
    }
}

// ---------------------------------------------------------------------------
// Kernel 1: software-pipelined persistent chamfer. 444 blocks (3/SM,
// lb(256,3) -> 85-reg budget) steal 1024 items. Next item's steal + raw-
// target staging (cp.async) are issued BEFORE the current hot loop and land
// during it -> per-item preamble latency hidden. Hot loop and atomicMax
// combine identical to R15. 2 bars/item.
// ---------------------------------------------------------------------------
__global__ void __launch_bounds__(TPB, 3) k_chamfer(
    const float* __restrict__ pred_rot,   const float* __restrict__ pred_trans,
    const float* __restrict__ ctx_hyp_rot,const float* __restrict__ ctx_hyp_trans,
    const float* __restrict__ gt_rot,     const float* __restrict__ gt_trans,
    const float* __restrict__ ctx_gt_rot, const float* __restrict__ ctx_gt_trans,
    const float* __restrict__ mp)
{
    __shared__ float4 s_xy[TILE_P];
    __shared__ float4 s_zh[TILE_P];
    __shared__ float  s_raw[TGT * 3];          // 3 KB raw target staging
    __shared__ float  sR[2][BB][9];
    __shared__ float  sT[2][BB][3];
    __shared__ int    s_next;

    const int tid = threadIdx.x;

    if (tid < 2 * BB)
        rel_transform_16(tid, pred_rot, pred_trans, ctx_hyp_rot, ctx_hyp_trans,
                         gt_rot, gt_trans, ctx_gt_rot, ctx_gt_trans, sR, sT);

    const uint raw_smem = (uint)__cvta_generic_to_shared(s_raw);

    // ---- prologue: steal item 0, stage its raw targets, steal item 1 ----
    if (tid == 0) s_next = (int)atomicAdd(&g_work, 1u);
    __syncthreads();                           // s_next + sR/sT visible
    int cur = s_next;
    if (cur < NITEMS && tid < (TGT * 3) / 4) {
        const int tc0 = cur & (NTCH - 1);
        const int b0  = (cur >> 6) & (BB - 1);
        cp_async16(raw_smem + tid * 16, mp + (b0 * NN + tc0 * TGT) * 3 + tid * 4);
    }
    cp_async_commit();
    if (tid == 0) s_next = (int)atomicAdd(&g_work, 1u);
    cp_async_wait0();
    __syncthreads();                           // raw(cur) ready; s_next visible

    while (cur < NITEMS) {
        const int tc  = cur & (NTCH - 1);
        const int qc  = (cur >> 4) & (NQCH - 1);
        const int b   = (cur >> 6) & (BB - 1);
        const int dir = cur >> 9;
        const int nxt = s_next;                // stolen last iteration

        // transform 2 targets per thread into packed tile (w = 1-dir)
        if (tid < TILE_P) {
            const float* R = sR[1 - dir][b];
            const float* t = sT[1 - dir][b];
            const int p = tid;
            float xx[2], yy[2], zz[2], hh[2];
            #pragma unroll
            for (int l = 0; l < 2; l++) {
                const float px = s_raw[(2*p + l)*3 + 0];
                const float py = s_raw[(2*p + l)*3 + 1];
                const float pz = s_raw[(2*p + l)*3 + 2];
                float x = fmaf(R[0], px, fmaf(R[1], py, fmaf(R[2], pz, t[0])));
                float y = fmaf(R[3], px, fmaf(R[4], py, fmaf(R[5], pz, t[1])));
                float z = fmaf(R[6], px, fmaf(R[7], py, fmaf(R[8], pz, t[2])));
                xx[l] = x; yy[l] = y; zz[l] = z;
                hh[l] = 0.5f * fmaf(x, x, fmaf(y, y, z * z));
            }
            s_xy[p] = make_float4(xx[0], xx[1], yy[0], yy[1]);
            s_zh[p] = make_float4(zz[0], zz[1], hh[0], hh[1]);
        }

        // transform 4 queries per thread (w = dir), packed-negated + h
        const int nbase = qc * QPB + tid;
        ull nx[QPT], ny[QPT], nz[QPT];
        float hq[QPT];
        {
            const float* R = sR[dir][b];
            const float* t = sT[dir][b];
            #pragma unroll
            for (int k = 0; k < QPT; k++) {
                const float* p = mp + (b * NN + nbase + k * TPB) * 3;
                const float px = p[0], py = p[1], pz = p[2];
                float x = fmaf(R[0], px, fmaf(R[1], py, fmaf(R[2], pz, t[0])));
                float y = fmaf(R[3], px, fmaf(R[4], py, fmaf(R[5], pz, t[1])));
                float z = fmaf(R[6], px, fmaf(R[7], py, fmaf(R[8], pz, t[2])));
                hq[k] = 0.5f * fmaf(x, x, fmaf(y, y, z * z));
                nx[k] = pack2(-x, -x);
                ny[k] = pack2(-y, -y);
                nz[k] = pack2(-z, -z);
            }
        }

        __syncthreads();      // tile visible to all; raw free for overwrite

        // prefetch next item's raw targets (lands during the hot loop)
        if (nxt < NITEMS && tid < (TGT * 3) / 4) {
            const int tcn = nxt & (NTCH - 1);
            const int bn  = (nxt >> 6) & (BB - 1);
            cp_async16(raw_smem + tid * 16, mp + (bn * NN + tcn * TGT) * 3 + tid * 4);
        }
        cp_async_commit();
        // steal the item after next (visible after end-of-iter bar)
        if (tid == 0) s_next = (int)atomicAdd(&g_work, 1u);

        float ma[QPT], mb[QPT];
        #pragma unroll
        for (int k = 0; k < QPT; k++) { ma[k] = INFINITY; mb[k] = INFINITY; }

        const ulonglong2* __restrict__ axy = (const ulonglong2*)s_xy;
        const ulonglong2* __restrict__ azh = (const ulonglong2*)s_zh;

        #pragma unroll 4
        for (int j = 0; j < TILE_P; j++) {
            const ulonglong2 A = axy[j];   // (x0,x1) (y0,y1)
            const ulonglong2 B = azh[j];   // (z0,z1) (h0,h1)
            #pragma unroll
            for (int k = 0; k < QPT; k++) {
                ull v = fma2(nz[k], B.x, B.y);
                v = fma2(ny[k], A.y, v);
                v = fma2(nx[k], A.x, v);
                float lo, hi;
                unpack2(v, lo, hi);
                ma[k] = fminf(ma[k], lo);
                mb[k] = fminf(mb[k], hi);
            }
        }

        // exact deterministic min-combine: atomicMax on complement-encoding
        {
            const int db = dir * BB + b;
            #pragma unroll
            for (int k = 0; k < QPT; k++) {
                const uint key = ~enc_f(fminf(ma[k], mb[k]) + hq[k]);
                atomicMax(&g_menc[db * NN + nbase + k * TPB], key);
            }
        }

        cp_async_wait0();     // raw(nxt) arrived
        __syncthreads();      // raw + s_next visible; tile reads complete
        cur = nxt;
    }
}

// ---------------------------------------------------------------------------
// Deterministic block sum reduction (valid in thread 0)
// ---------------------------------------------------------------------------
__device__ __forceinline__ float block_reduce_sum(float v)
{
    __shared__ float ws[TPB / 32];
    #pragma unroll
    for (int o = 16; o > 0; o >>= 1) v += __shfl_down_sync(0xffffffffu, v, o);
    if ((threadIdx.x & 31) == 0) ws[threadIdx.x >> 5] = v;
    __syncthreads();
    if (threadIdx.x < 32) {
        v = (threadIdx.x < TPB / 32) ? ws[threadIdx.x] : 0.f;
        #pragma unroll
        for (int o = 4; o > 0; o >>= 1) v += __shfl_down_sync(0xffffffffu, v, o);
    }
    return v;
}

// ---------------------------------------------------------------------------
// Kernel 2 (PDL secondary): loss_trans BEFORE the grid-dependency sync,
// then read+reset g_menc (one uint4/thread), deferred sqrt, fixed-order
// final sum in the last-done block. Resets g_work/g_done for the next replay.
// ---------------------------------------------------------------------------
__global__ void __launch_bounds__(TPB) k_reduce(
    const float* __restrict__ pred_rot,   const float* __restrict__ pred_trans,
    const float* __restrict__ ctx_hyp_rot,const float* __restrict__ ctx_hyp_trans,
    const float* __restrict__ gt_rot,     const float* __restrict__ gt_trans,
    const float* __restrict__ ctx_gt_rot, const float* __restrict__ ctx_gt_trans,
    float* __restrict__ out)
{
    const int tid = threadIdx.x;

    // independent preamble: loss_trans in block 0 (overlaps chamfer tail)
    __shared__ float sR[2][BB][9];
    __shared__ float sT[2][BB][3];
    if (blockIdx.x == 0) {
        if (tid < 2 * BB)
            rel_transform_16(tid, pred_rot, pred_trans, ctx_hyp_rot, ctx_hyp_trans,
                             gt_rot, gt_trans, ctx_gt_rot, ctx_gt_trans, sR, sT);
        __syncthreads();
        if (tid == 0) {
            float lt = 0.f;
            #pragma unroll
            for (int bb = 0; bb < BB; bb++)
                #pragma unroll
                for (int i = 0; i < 3; i++)
                    lt += fabsf(sT[0][bb][i] - sT[1][bb][i]);
            out[1] = lt * (1.0f / (BB * 3));
        }
    }

    // wait for chamfer's writes to be visible
    cudaGridDependencySynchronize();

    // one uint4 per thread: 64 blk * 256 thr * 4 = 65536 slots
    const int i = blockIdx.x * TPB + tid;
    uint4* __restrict__ me4 = (uint4*)g_menc;
    const uint4 kv = __ldcg(&me4[i]);
    me4[i] = make_uint4(0u, 0u, 0u, 0u);     // reset for next replay
    float s = sqrtf(fmaxf(2.0f * dec_f(~kv.x), 0.0f))
            + sqrtf(fmaxf(2.0f * dec_f(~kv.y), 0.0f))
            + sqrtf(fmaxf(2.0f * dec_f(~kv.z), 0.0f))
            + sqrtf(fmaxf(2.0f * dec_f(~kv.w), 0.0f));

    float bs = block_reduce_sum(s);

    __shared__ bool is_last;
    if (tid == 0) {
        g_partials[blockIdx.x] = bs;
        __threadfence();
        is_last = (atomicAdd(&g_done, 1u) == NRED_BLK - 1);
    }
    __syncthreads();

    if (is_last) {
        const volatile float* vp = g_partials;
        float v = (tid < NRED_BLK) ? vp[tid] : 0.f;
        float tot = block_reduce_sum(v);
        if (tid == 0) {
            out[0] = tot * (1.0f / (BB * NN));
            g_work = 0;   // reset work counter for next replay
            g_done = 0;   // reset completion counter for next replay
        }
    }
}

// ---------------------------------------------------------------------------
extern "C" void kernel_launch(void* const* d_in, const int* in_sizes, int n_in,
                              void* d_out, int out_size)
{
    const float* pred_rot      = (const float*)d_in[0];
    const float* pred_trans    = (const float*)d_in[1];
    const float* ctx_hyp_rot   = (const float*)d_in[2];
    const float* ctx_hyp_trans = (const float*)d_in[3];
    const float* gt_rot        = (const float*)d_in[4];
    const float* gt_trans      = (const float*)d_in[5];
    const float* ctx_gt_rot    = (const float*)d_in[6];
    const float* ctx_gt_trans  = (const float*)d_in[7];
    const float* model_points  = (const float*)d_in[8];
    float* out = (float*)d_out;

    k_chamfer<<<NBLK_CH, TPB>>>(
        pred_rot, pred_trans, ctx_hyp_rot, ctx_hyp_trans,
        gt_rot, gt_trans, ctx_gt_rot, ctx_gt_trans, model_points);

    // PDL launch: overlap reduce's launch + loss_trans with the chamfer tail
    cudaLaunchConfig_t cfg = {};
    cfg.gridDim  = dim3(NRED_BLK, 1, 1);
    cfg.blockDim = dim3(TPB, 1, 1);
    cfg.dynamicSmemBytes = 0;
    cfg.stream = 0;
    cudaLaunchAttribute attrs[1];
    attrs[0].id = cudaLaunchAttributeProgrammaticStreamSerialization;
    attrs[0].val.programmaticStreamSerializationAllowed = 1;
    cfg.attrs = attrs;
    cfg.numAttrs = 1;
    cudaLaunchKernelEx(&cfg, k_reduce,
                       pred_rot, pred_trans, ctx_hyp_rot, ctx_hyp_trans,
                       gt_rot, gt_trans, ctx_gt_rot, ctx_gt_trans, out);
}